// round 16
// baseline (speedup 1.0000x reference)
#include <cuda_runtime.h>
#include <math.h>

#define T_FRAMES 128
#define V_VERTS  5023
#define V_PAD    5024
#define K_NBR    16
#define BLOCK    1024

// smem: sA[V_PAD] float4 (cx,cy,cz,dx) | sB[V_PAD] float2 (dy,dz)
#define SMEM_BYTES (V_PAD * (16 + 8))

// packed (neighbor | mask<<31), slot-major [k][v] for coalesced warp reads
__device__ int g_packed[K_NBR * V_PAD];

__global__ void __launch_bounds__(256)
pack_kernel(const int* __restrict__ neighbors, const int* __restrict__ nmask)
{
    int i = blockIdx.x * blockDim.x + threadIdx.x;   // i = k*V + v (coalesced writes)
    if (i >= K_NBR * V_VERTS) return;
    int k = i / V_VERTS;
    int v = i - k * V_VERTS;
    int n = neighbors[v * K_NBR + k];
    int m = nmask[v * K_NBR + k];
    g_packed[k * V_PAD + v] = n | (m ? 0x80000000 : 0);
}

__device__ __forceinline__ void jacobi_rotate(float S[3][3], float Vm[3][3], int p, int q) {
    float Spq = S[p][q];
    float tau = __fdividef(S[q][q] - S[p][p], 2.0f * Spq);
    float at = fabsf(tau);
    float t = __fdividef(1.0f, at + sqrtf(1.0f + at * at));
    t = (tau < 0.0f) ? -t : t;
    t = (fabsf(Spq) < 1e-25f) ? 0.0f : t;
    float c = rsqrtf(1.0f + t * t);
    float s = t * c;

    float Spp = S[p][p], Sqq = S[q][q];
    S[p][p] = Spp - t * Spq;
    S[q][q] = Sqq + t * Spq;
    S[p][q] = 0.0f;
    S[q][p] = 0.0f;
    int r = 3 - p - q;
    float Srp = S[r][p], Srq = S[r][q];
    S[r][p] = c * Srp - s * Srq;  S[p][r] = S[r][p];
    S[r][q] = s * Srp + c * Srq;  S[q][r] = S[r][q];

    #pragma unroll
    for (int i = 0; i < 3; i++) {
        float vip = Vm[i][p], viq = Vm[i][q];
        Vm[i][p] = c * vip - s * viq;
        Vm[i][q] = s * vip + c * viq;
    }
}

// Slow-path: full Jacobi SVD rotation extraction (handles det<=0 / degenerate).
__device__ __forceinline__ void svd_rotation_fallback(const float A[3][3], float R[3][3]) {
    float S[3][3];
    #pragma unroll
    for (int i = 0; i < 3; i++)
        #pragma unroll
        for (int j = 0; j < 3; j++) {
            float acc = 0.0f;
            #pragma unroll
            for (int k = 0; k < 3; k++) acc += A[k][i] * A[k][j];
            S[i][j] = acc;
        }

    float Vm[3][3] = {{1, 0, 0}, {0, 1, 0}, {0, 0, 1}};
    #pragma unroll
    for (int sweep = 0; sweep < 5; sweep++) {
        jacobi_rotate(S, Vm, 0, 1);
        jacobi_rotate(S, Vm, 0, 2);
        jacobi_rotate(S, Vm, 1, 2);
    }

    float w0 = S[0][0], w1 = S[1][1], w2 = S[2][2];
    float c00 = Vm[0][0], c01 = Vm[1][0], c02 = Vm[2][0];
    float c10 = Vm[0][1], c11 = Vm[1][1], c12 = Vm[2][1];
    float c20 = Vm[0][2], c21 = Vm[1][2], c22 = Vm[2][2];
    {
        bool sw = w0 < w1;
        float tw = sw ? w1 : w0;  w1 = sw ? w0 : w1;  w0 = tw;
        float tx = sw ? c10 : c00, ty = sw ? c11 : c01, tz = sw ? c12 : c02;
        c10 = sw ? c00 : c10; c11 = sw ? c01 : c11; c12 = sw ? c02 : c12;
        c00 = tx; c01 = ty; c02 = tz;
    }
    {
        bool sw = w0 < w2;
        float tw = sw ? w2 : w0;  w2 = sw ? w0 : w2;  w0 = tw;
        float tx = sw ? c20 : c00, ty = sw ? c21 : c01, tz = sw ? c22 : c02;
        c20 = sw ? c00 : c20; c21 = sw ? c01 : c21; c22 = sw ? c02 : c22;
        c00 = tx; c01 = ty; c02 = tz;
    }
    {
        bool sw = w1 < w2;
        float tw = sw ? w2 : w1;  w2 = sw ? w1 : w2;  w1 = tw;
        float tx = sw ? c20 : c10, ty = sw ? c21 : c11, tz = sw ? c22 : c12;
        c20 = sw ? c10 : c20; c21 = sw ? c11 : c21; c22 = sw ? c12 : c22;
        c10 = tx; c11 = ty; c12 = tz;
    }
    float V0[3] = {c00, c01, c02};
    float V1[3] = {c10, c11, c12};
    float V2[3] = {c20, c21, c22};

    float U0[3], U1[3], U2[3];
    #pragma unroll
    for (int i = 0; i < 3; i++) {
        U0[i] = A[i][0] * V0[0] + A[i][1] * V0[1] + A[i][2] * V0[2];
        U1[i] = A[i][0] * V1[0] + A[i][1] * V1[1] + A[i][2] * V1[2];
        U2[i] = A[i][0] * V2[0] + A[i][1] * V2[1] + A[i][2] * V2[2];
    }
    float n0 = U0[0]*U0[0] + U0[1]*U0[1] + U0[2]*U0[2];
    float n1 = U1[0]*U1[0] + U1[1]*U1[1] + U1[2]*U1[2];
    float n2 = U2[0]*U2[0] + U2[1]*U2[1] + U2[2]*U2[2];

    if (n0 < 1e-30f) {
        R[0][0] = 1; R[0][1] = 0; R[0][2] = 0;
        R[1][0] = 0; R[1][1] = 1; R[1][2] = 0;
        R[2][0] = 0; R[2][1] = 0; R[2][2] = 1;
        return;
    }
    float inv0 = rsqrtf(n0);
    #pragma unroll
    for (int i = 0; i < 3; i++) U0[i] *= inv0;
    if (n1 > 1e-12f * n0) {
        float inv1 = rsqrtf(n1);
        #pragma unroll
        for (int i = 0; i < 3; i++) U1[i] *= inv1;
    } else {
        float ax = fabsf(U0[0]), ay = fabsf(U0[1]), az = fabsf(U0[2]);
        float e[3] = {0, 0, 0};
        if (ax <= ay && ax <= az) e[0] = 1; else if (ay <= az) e[1] = 1; else e[2] = 1;
        float d = e[0]*U0[0] + e[1]*U0[1] + e[2]*U0[2];
        float tx = e[0] - d*U0[0], ty = e[1] - d*U0[1], tz = e[2] - d*U0[2];
        float inr = rsqrtf(tx*tx + ty*ty + tz*tz);
        U1[0] = tx * inr; U1[1] = ty * inr; U1[2] = tz * inr;
    }
    if (n2 > 1e-12f * n0) {
        float inv2 = rsqrtf(n2);
        #pragma unroll
        for (int i = 0; i < 3; i++) U2[i] *= inv2;
    } else {
        U2[0] = U0[1]*U1[2] - U0[2]*U1[1];
        U2[1] = U0[2]*U1[0] - U0[0]*U1[2];
        U2[2] = U0[0]*U1[1] - U0[1]*U1[0];
    }

    float detU = U0[0]*(U1[1]*U2[2] - U1[2]*U2[1])
               - U0[1]*(U1[0]*U2[2] - U1[2]*U2[0])
               + U0[2]*(U1[0]*U2[1] - U1[1]*U2[0]);
    float detV = V0[0]*(V1[1]*V2[2] - V1[2]*V2[1])
               - V0[1]*(V1[0]*V2[2] - V1[2]*V2[0])
               + V0[2]*(V1[0]*V2[1] - V1[1]*V2[0]);
    float detUV = detU * detV;
    float d3 = (fabsf(detUV - 1.0f) > 1e-6f) ? detUV : 1.0f;

    #pragma unroll
    for (int a = 0; a < 3; a++)
        #pragma unroll
        for (int b = 0; b < 3; b++)
            R[a][b] = V0[a]*U0[b] + V1[a]*U1[b] + d3 * V2[a]*U2[b];
}

__global__ void __launch_bounds__(BLOCK, 1)
se3_extract_kernel(const float* __restrict__ canon,
                   const float* __restrict__ deform,
                   float* __restrict__ rot_out,
                   float* __restrict__ trn_out)
{
    extern __shared__ char smem_raw[];
    float4* sA = (float4*)smem_raw;          // (cx, cy, cz, dx)
    float2* sB = (float2*)(sA + V_PAD);      // (dy, dz)

    int t   = blockIdx.x;
    int tid = threadIdx.x;

    const float* ct = canon  + (size_t)t * V_VERTS * 3;
    const float* dt = deform + (size_t)t * V_VERTS * 3;

    for (int v = tid; v < V_VERTS; v += BLOCK) {
        float x = ct[v * 3 + 0], y = ct[v * 3 + 1], z = ct[v * 3 + 2];
        float xd = dt[v * 3 + 0], yd = dt[v * 3 + 1], zd = dt[v * 3 + 2];
        sA[v] = make_float4(x, y, z, xd);
        sB[v] = make_float2(yd, zd);
    }
    __syncthreads();

    for (int v = tid; v < V_VERTS; v += BLOCK) {
        // covariance via expansion:
        //   cov = sum m*cn*dn^T - (sum m*cn) d0^T - c0 (sum m*dn)^T + K*c0*d0^T
        float a00 = 0.f, a01 = 0.f, a02 = 0.f;
        float a10 = 0.f, a11 = 0.f, a12 = 0.f;
        float a20 = 0.f, a21 = 0.f, a22 = 0.f;
        float scx = 0.f, scy = 0.f, scz = 0.f;
        float sdx = 0.f, sdy = 0.f, sdz = 0.f;

        #pragma unroll
        for (int k = 0; k < K_NBR; k++) {
            int packed = __ldg(&g_packed[k * V_PAD + v]);   // coalesced: 1 line/warp
            float m = (packed < 0) ? 1.0f : 0.0f;           // mask from sign bit
            int n = packed & 0x7FFFFFFF;
            float4 pa = sA[n];     // cx cy cz dx
            float2 pb = sB[n];     // dy dz
            float mcx = pa.x * m, mcy = pa.y * m, mcz = pa.z * m;
            scx += mcx; scy += mcy; scz += mcz;
            sdx += pa.w * m; sdy += pb.x * m; sdz += pb.y * m;
            a00 += mcx * pa.w; a01 += mcx * pb.x; a02 += mcx * pb.y;
            a10 += mcy * pa.w; a11 += mcy * pb.x; a12 += mcy * pb.y;
            a20 += mcz * pa.w; a21 += mcz * pb.x; a22 += mcz * pb.y;
        }

        float4 pa0 = sA[v];
        float2 pb0 = sB[v];
        float c0x = pa0.x, c0y = pa0.y, c0z = pa0.z;
        float d0x = pa0.w, d0y = pb0.x, d0z = pb0.y;
        float gx = (float)K_NBR * c0x - scx;
        float gy = (float)K_NBR * c0y - scy;
        float gz = (float)K_NBR * c0z - scz;
        a00 += gx * d0x - c0x * sdx;  a01 += gx * d0y - c0x * sdy;  a02 += gx * d0z - c0x * sdz;
        a10 += gy * d0x - c0y * sdx;  a11 += gy * d0y - c0y * sdy;  a12 += gy * d0z - c0y * sdz;
        a20 += gz * d0x - c0z * sdx;  a21 += gz * d0y - c0z * sdy;  a22 += gz * d0z - c0z * sdz;

        float A[3][3] = {{a00, a01, a02}, {a10, a11, a12}, {a20, a21, a22}};

        // ---- rotation via det-scaled Newton polar iteration on X0 = A^T ----
        float R[3][3];

        float frob = a00*a00 + a01*a01 + a02*a02
                   + a10*a10 + a11*a11 + a12*a12
                   + a20*a20 + a21*a21 + a22*a22;
        float invf = rsqrtf(fmaxf(frob, 1e-30f));

        float X00 = a00 * invf, X01 = a10 * invf, X02 = a20 * invf;
        float X10 = a01 * invf, X11 = a11 * invf, X12 = a21 * invf;
        float X20 = a02 * invf, X21 = a12 * invf, X22 = a22 * invf;

        float det0 = X00 * (X11*X22 - X12*X21)
                   - X01 * (X10*X22 - X12*X20)
                   + X02 * (X10*X21 - X11*X20);

        if (det0 > 1e-5f) {
            #pragma unroll
            for (int it = 0; it < 5; it++) {
                float C00 = X11*X22 - X12*X21;
                float C01 = X12*X20 - X10*X22;
                float C02 = X10*X21 - X11*X20;
                float C10 = X02*X21 - X01*X22;
                float C11 = X00*X22 - X02*X20;
                float C12 = X01*X20 - X00*X21;
                float C20 = X01*X12 - X02*X11;
                float C21 = X02*X10 - X00*X12;
                float C22 = X00*X11 - X01*X10;
                float det = X00*C00 + X01*C01 + X02*C02;
                float g = __expf(-0.33333333f * __logf(det));
                float h = 0.5f * g;
                float r = __fdividef(0.5f, det * g);
                X00 = h*X00 + r*C00;  X01 = h*X01 + r*C01;  X02 = h*X02 + r*C02;
                X10 = h*X10 + r*C10;  X11 = h*X11 + r*C11;  X12 = h*X12 + r*C12;
                X20 = h*X20 + r*C20;  X21 = h*X21 + r*C21;  X22 = h*X22 + r*C22;
            }
            R[0][0] = X00; R[0][1] = X01; R[0][2] = X02;
            R[1][0] = X10; R[1][1] = X11; R[1][2] = X12;
            R[2][0] = X20; R[2][1] = X21; R[2][2] = X22;
        } else {
            svd_rotation_fallback(A, R);
        }

        // ---- matrix -> quaternion ----
        float m00 = R[0][0], m01 = R[0][1], m02 = R[0][2];
        float m10 = R[1][0], m11 = R[1][1], m12 = R[1][2];
        float m20 = R[2][0], m21 = R[2][1], m22 = R[2][2];

        float qa0 = sqrtf(fmaxf(1.0f + m00 + m11 + m22, 0.0f));
        float qa1 = sqrtf(fmaxf(1.0f + m00 - m11 - m22, 0.0f));
        float qa2 = sqrtf(fmaxf(1.0f - m00 + m11 - m22, 0.0f));
        float qa3 = sqrtf(fmaxf(1.0f - m00 - m11 + m22, 0.0f));

        int imax = 0; float qmax = qa0;
        imax = (qa1 > qmax) ? 1 : imax;  qmax = (qa1 > qmax) ? qa1 : qmax;
        imax = (qa2 > qmax) ? 2 : imax;  qmax = (qa2 > qmax) ? qa2 : qmax;
        imax = (qa3 > qmax) ? 3 : imax;  qmax = (qa3 > qmax) ? qa3 : qmax;

        bool b0 = (imax == 0), b1 = (imax == 1), b2 = (imax == 2);
        float cand0 = b0 ? qa0 * qa0 : (b1 ? m21 - m12 : (b2 ? m02 - m20 : m10 - m01));
        float cand1 = b0 ? m21 - m12 : (b1 ? qa1 * qa1 : (b2 ? m10 + m01 : m20 + m02));
        float cand2 = b0 ? m02 - m20 : (b1 ? m01 + m10 : (b2 ? qa2 * qa2 : m21 + m12));
        float cand3 = b0 ? m10 - m01 : (b1 ? m02 + m20 : (b2 ? m12 + m21 : qa3 * qa3));

        float invd = __fdividef(1.0f, 2.0f * fmaxf(qmax, 0.1f));

        size_t tv = (size_t)t * V_VERTS + v;
        ((float4*)rot_out)[tv] = make_float4(cand0 * invd, cand1 * invd,
                                             cand2 * invd, cand3 * invd);
        trn_out[tv * 3 + 0] = d0x - c0x;
        trn_out[tv * 3 + 1] = d0y - c0y;
        trn_out[tv * 3 + 2] = d0z - c0z;
    }
}

extern "C" void kernel_launch(void* const* d_in, const int* in_sizes, int n_in,
                              void* d_out, int out_size) {
    const float* canon  = (const float*)d_in[0];
    const float* deform = (const float*)d_in[1];
    const int*   neigh  = (const int*)d_in[2];
    const int*   nmask  = (const int*)d_in[3];
    float* out = (float*)d_out;
    float* rot_out = out;                                   // [T*V, 4]
    float* trn_out = out + (size_t)T_FRAMES * V_VERTS * 4;  // [T*V, 3]

    static bool attr_set = false;
    if (!attr_set) {
        cudaFuncSetAttribute(se3_extract_kernel,
                             cudaFuncAttributeMaxDynamicSharedMemorySize, SMEM_BYTES);
        attr_set = true;
    }

    int pack_n = K_NBR * V_VERTS;
    pack_kernel<<<(pack_n + 255) / 256, 256>>>(neigh, nmask);
    se3_extract_kernel<<<T_FRAMES, BLOCK, SMEM_BYTES>>>(canon, deform, rot_out, trn_out);
}

// round 17
// speedup vs baseline: 1.1199x; 1.1199x over previous
#include <cuda_runtime.h>
#include <math.h>

#define T_FRAMES 128
#define V_VERTS  5023
#define V_PAD    5024
#define K_NBR    16
#define BLOCK    768

// smem: sA[V_PAD] float4 (cx,cy,cz,dx) | sB[V_PAD] float2 (dy,dz)
#define SMEM_BYTES (V_PAD * (16 + 8))

// packed (neighbor | mask<<31), slot-major [k][v] for coalesced warp reads
__device__ int g_packed[K_NBR * V_PAD];

__global__ void __launch_bounds__(256)
pack_kernel(const int* __restrict__ neighbors, const int* __restrict__ nmask)
{
    int i = blockIdx.x * blockDim.x + threadIdx.x;   // i = k*V + v (coalesced writes)
    if (i >= K_NBR * V_VERTS) return;
    int k = i / V_VERTS;
    int v = i - k * V_VERTS;
    int n = neighbors[v * K_NBR + k];
    int m = nmask[v * K_NBR + k];
    g_packed[k * V_PAD + v] = n | (m ? 0x80000000 : 0);
}

__device__ __forceinline__ void jacobi_rotate(float S[3][3], float Vm[3][3], int p, int q) {
    float Spq = S[p][q];
    float tau = __fdividef(S[q][q] - S[p][p], 2.0f * Spq);
    float at = fabsf(tau);
    float t = __fdividef(1.0f, at + sqrtf(1.0f + at * at));
    t = (tau < 0.0f) ? -t : t;
    t = (fabsf(Spq) < 1e-25f) ? 0.0f : t;
    float c = rsqrtf(1.0f + t * t);
    float s = t * c;

    float Spp = S[p][p], Sqq = S[q][q];
    S[p][p] = Spp - t * Spq;
    S[q][q] = Sqq + t * Spq;
    S[p][q] = 0.0f;
    S[q][p] = 0.0f;
    int r = 3 - p - q;
    float Srp = S[r][p], Srq = S[r][q];
    S[r][p] = c * Srp - s * Srq;  S[p][r] = S[r][p];
    S[r][q] = s * Srp + c * Srq;  S[q][r] = S[r][q];

    #pragma unroll
    for (int i = 0; i < 3; i++) {
        float vip = Vm[i][p], viq = Vm[i][q];
        Vm[i][p] = c * vip - s * viq;
        Vm[i][q] = s * vip + c * viq;
    }
}

// Slow-path: full Jacobi SVD rotation extraction (handles det<=0 / degenerate).
__device__ __forceinline__ void svd_rotation_fallback(const float A[3][3], float R[3][3]) {
    float S[3][3];
    #pragma unroll
    for (int i = 0; i < 3; i++)
        #pragma unroll
        for (int j = 0; j < 3; j++) {
            float acc = 0.0f;
            #pragma unroll
            for (int k = 0; k < 3; k++) acc += A[k][i] * A[k][j];
            S[i][j] = acc;
        }

    float Vm[3][3] = {{1, 0, 0}, {0, 1, 0}, {0, 0, 1}};
    #pragma unroll
    for (int sweep = 0; sweep < 5; sweep++) {
        jacobi_rotate(S, Vm, 0, 1);
        jacobi_rotate(S, Vm, 0, 2);
        jacobi_rotate(S, Vm, 1, 2);
    }

    float w0 = S[0][0], w1 = S[1][1], w2 = S[2][2];
    float c00 = Vm[0][0], c01 = Vm[1][0], c02 = Vm[2][0];
    float c10 = Vm[0][1], c11 = Vm[1][1], c12 = Vm[2][1];
    float c20 = Vm[0][2], c21 = Vm[1][2], c22 = Vm[2][2];
    {
        bool sw = w0 < w1;
        float tw = sw ? w1 : w0;  w1 = sw ? w0 : w1;  w0 = tw;
        float tx = sw ? c10 : c00, ty = sw ? c11 : c01, tz = sw ? c12 : c02;
        c10 = sw ? c00 : c10; c11 = sw ? c01 : c11; c12 = sw ? c02 : c12;
        c00 = tx; c01 = ty; c02 = tz;
    }
    {
        bool sw = w0 < w2;
        float tw = sw ? w2 : w0;  w2 = sw ? w0 : w2;  w0 = tw;
        float tx = sw ? c20 : c00, ty = sw ? c21 : c01, tz = sw ? c22 : c02;
        c20 = sw ? c00 : c20; c21 = sw ? c01 : c21; c22 = sw ? c02 : c22;
        c00 = tx; c01 = ty; c02 = tz;
    }
    {
        bool sw = w1 < w2;
        float tw = sw ? w2 : w1;  w2 = sw ? w1 : w2;  w1 = tw;
        float tx = sw ? c20 : c10, ty = sw ? c21 : c11, tz = sw ? c22 : c12;
        c20 = sw ? c10 : c20; c21 = sw ? c11 : c21; c22 = sw ? c12 : c22;
        c10 = tx; c11 = ty; c12 = tz;
    }
    float V0[3] = {c00, c01, c02};
    float V1[3] = {c10, c11, c12};
    float V2[3] = {c20, c21, c22};

    float U0[3], U1[3], U2[3];
    #pragma unroll
    for (int i = 0; i < 3; i++) {
        U0[i] = A[i][0] * V0[0] + A[i][1] * V0[1] + A[i][2] * V0[2];
        U1[i] = A[i][0] * V1[0] + A[i][1] * V1[1] + A[i][2] * V1[2];
        U2[i] = A[i][0] * V2[0] + A[i][1] * V2[1] + A[i][2] * V2[2];
    }
    float n0 = U0[0]*U0[0] + U0[1]*U0[1] + U0[2]*U0[2];
    float n1 = U1[0]*U1[0] + U1[1]*U1[1] + U1[2]*U1[2];
    float n2 = U2[0]*U2[0] + U2[1]*U2[1] + U2[2]*U2[2];

    if (n0 < 1e-30f) {
        R[0][0] = 1; R[0][1] = 0; R[0][2] = 0;
        R[1][0] = 0; R[1][1] = 1; R[1][2] = 0;
        R[2][0] = 0; R[2][1] = 0; R[2][2] = 1;
        return;
    }
    float inv0 = rsqrtf(n0);
    #pragma unroll
    for (int i = 0; i < 3; i++) U0[i] *= inv0;
    if (n1 > 1e-12f * n0) {
        float inv1 = rsqrtf(n1);
        #pragma unroll
        for (int i = 0; i < 3; i++) U1[i] *= inv1;
    } else {
        float ax = fabsf(U0[0]), ay = fabsf(U0[1]), az = fabsf(U0[2]);
        float e[3] = {0, 0, 0};
        if (ax <= ay && ax <= az) e[0] = 1; else if (ay <= az) e[1] = 1; else e[2] = 1;
        float d = e[0]*U0[0] + e[1]*U0[1] + e[2]*U0[2];
        float tx = e[0] - d*U0[0], ty = e[1] - d*U0[1], tz = e[2] - d*U0[2];
        float inr = rsqrtf(tx*tx + ty*ty + tz*tz);
        U1[0] = tx * inr; U1[1] = ty * inr; U1[2] = tz * inr;
    }
    if (n2 > 1e-12f * n0) {
        float inv2 = rsqrtf(n2);
        #pragma unroll
        for (int i = 0; i < 3; i++) U2[i] *= inv2;
    } else {
        U2[0] = U0[1]*U1[2] - U0[2]*U1[1];
        U2[1] = U0[2]*U1[0] - U0[0]*U1[2];
        U2[2] = U0[0]*U1[1] - U0[1]*U1[0];
    }

    float detU = U0[0]*(U1[1]*U2[2] - U1[2]*U2[1])
               - U0[1]*(U1[0]*U2[2] - U1[2]*U2[0])
               + U0[2]*(U1[0]*U2[1] - U1[1]*U2[0]);
    float detV = V0[0]*(V1[1]*V2[2] - V1[2]*V2[1])
               - V0[1]*(V1[0]*V2[2] - V1[2]*V2[0])
               + V0[2]*(V1[0]*V2[1] - V1[1]*V2[0]);
    float detUV = detU * detV;
    float d3 = (fabsf(detUV - 1.0f) > 1e-6f) ? detUV : 1.0f;

    #pragma unroll
    for (int a = 0; a < 3; a++)
        #pragma unroll
        for (int b = 0; b < 3; b++)
            R[a][b] = V0[a]*U0[b] + V1[a]*U1[b] + d3 * V2[a]*U2[b];
}

__global__ void __launch_bounds__(BLOCK, 1)
se3_extract_kernel(const float* __restrict__ canon,
                   const float* __restrict__ deform,
                   float* __restrict__ rot_out,
                   float* __restrict__ trn_out)
{
    extern __shared__ char smem_raw[];
    float4* sA = (float4*)smem_raw;          // (cx, cy, cz, dx)
    float2* sB = (float2*)(sA + V_PAD);      // (dy, dz)

    int t   = blockIdx.x;
    int tid = threadIdx.x;

    const float* ct = canon  + (size_t)t * V_VERTS * 3;
    const float* dt = deform + (size_t)t * V_VERTS * 3;

    for (int v = tid; v < V_VERTS; v += BLOCK) {
        float x = ct[v * 3 + 0], y = ct[v * 3 + 1], z = ct[v * 3 + 2];
        float xd = dt[v * 3 + 0], yd = dt[v * 3 + 1], zd = dt[v * 3 + 2];
        sA[v] = make_float4(x, y, z, xd);
        sB[v] = make_float2(yd, zd);
    }
    __syncthreads();

    for (int v = tid; v < V_VERTS; v += BLOCK) {
        // covariance via expansion (masked slots contribute exactly 0, so
        // their loads/FMAs are predicated away entirely):
        //   cov = sum_m cn*dn^T - (sum_m cn) d0^T - c0 (sum_m dn)^T + K*c0*d0^T
        float a00 = 0.f, a01 = 0.f, a02 = 0.f;
        float a10 = 0.f, a11 = 0.f, a12 = 0.f;
        float a20 = 0.f, a21 = 0.f, a22 = 0.f;
        float scx = 0.f, scy = 0.f, scz = 0.f;
        float sdx = 0.f, sdy = 0.f, sdz = 0.f;

        #pragma unroll
        for (int k = 0; k < K_NBR; k++) {
            int packed = __ldg(&g_packed[k * V_PAD + v]);   // coalesced: 1 line/warp
            if (packed < 0) {                               // mask bit set
                int n = packed & 0x7FFFFFFF;
                float4 pa = sA[n];     // cx cy cz dx
                float2 pb = sB[n];     // dy dz
                scx += pa.x; scy += pa.y; scz += pa.z;
                sdx += pa.w; sdy += pb.x; sdz += pb.y;
                a00 += pa.x * pa.w; a01 += pa.x * pb.x; a02 += pa.x * pb.y;
                a10 += pa.y * pa.w; a11 += pa.y * pb.x; a12 += pa.y * pb.y;
                a20 += pa.z * pa.w; a21 += pa.z * pb.x; a22 += pa.z * pb.y;
            }
        }

        float4 pa0 = sA[v];
        float2 pb0 = sB[v];
        float c0x = pa0.x, c0y = pa0.y, c0z = pa0.z;
        float d0x = pa0.w, d0y = pb0.x, d0z = pb0.y;
        float gx = (float)K_NBR * c0x - scx;
        float gy = (float)K_NBR * c0y - scy;
        float gz = (float)K_NBR * c0z - scz;
        a00 += gx * d0x - c0x * sdx;  a01 += gx * d0y - c0x * sdy;  a02 += gx * d0z - c0x * sdz;
        a10 += gy * d0x - c0y * sdx;  a11 += gy * d0y - c0y * sdy;  a12 += gy * d0z - c0y * sdz;
        a20 += gz * d0x - c0z * sdx;  a21 += gz * d0y - c0z * sdy;  a22 += gz * d0z - c0z * sdz;

        float A[3][3] = {{a00, a01, a02}, {a10, a11, a12}, {a20, a21, a22}};

        // ---- rotation via det-scaled Newton polar iteration on X0 = A^T ----
        float R[3][3];

        float frob = a00*a00 + a01*a01 + a02*a02
                   + a10*a10 + a11*a11 + a12*a12
                   + a20*a20 + a21*a21 + a22*a22;
        float invf = rsqrtf(fmaxf(frob, 1e-30f));

        float X00 = a00 * invf, X01 = a10 * invf, X02 = a20 * invf;
        float X10 = a01 * invf, X11 = a11 * invf, X12 = a21 * invf;
        float X20 = a02 * invf, X21 = a12 * invf, X22 = a22 * invf;

        float det0 = X00 * (X11*X22 - X12*X21)
                   - X01 * (X10*X22 - X12*X20)
                   + X02 * (X10*X21 - X11*X20);

        if (det0 > 1e-5f) {
            #pragma unroll
            for (int it = 0; it < 4; it++) {
                float C00 = X11*X22 - X12*X21;
                float C01 = X12*X20 - X10*X22;
                float C02 = X10*X21 - X11*X20;
                float C10 = X02*X21 - X01*X22;
                float C11 = X00*X22 - X02*X20;
                float C12 = X01*X20 - X00*X21;
                float C20 = X01*X12 - X02*X11;
                float C21 = X02*X10 - X00*X12;
                float C22 = X00*X11 - X01*X10;
                float det = X00*C00 + X01*C01 + X02*C02;
                float g = __expf(-0.33333333f * __logf(det));
                float h = 0.5f * g;
                float r = __fdividef(0.5f, det * g);
                X00 = h*X00 + r*C00;  X01 = h*X01 + r*C01;  X02 = h*X02 + r*C02;
                X10 = h*X10 + r*C10;  X11 = h*X11 + r*C11;  X12 = h*X12 + r*C12;
                X20 = h*X20 + r*C20;  X21 = h*X21 + r*C21;  X22 = h*X22 + r*C22;
            }
            R[0][0] = X00; R[0][1] = X01; R[0][2] = X02;
            R[1][0] = X10; R[1][1] = X11; R[1][2] = X12;
            R[2][0] = X20; R[2][1] = X21; R[2][2] = X22;
        } else {
            svd_rotation_fallback(A, R);
        }

        // ---- matrix -> quaternion ----
        float m00 = R[0][0], m01 = R[0][1], m02 = R[0][2];
        float m10 = R[1][0], m11 = R[1][1], m12 = R[1][2];
        float m20 = R[2][0], m21 = R[2][1], m22 = R[2][2];

        float qa0 = sqrtf(fmaxf(1.0f + m00 + m11 + m22, 0.0f));
        float qa1 = sqrtf(fmaxf(1.0f + m00 - m11 - m22, 0.0f));
        float qa2 = sqrtf(fmaxf(1.0f - m00 + m11 - m22, 0.0f));
        float qa3 = sqrtf(fmaxf(1.0f - m00 - m11 + m22, 0.0f));

        int imax = 0; float qmax = qa0;
        imax = (qa1 > qmax) ? 1 : imax;  qmax = (qa1 > qmax) ? qa1 : qmax;
        imax = (qa2 > qmax) ? 2 : imax;  qmax = (qa2 > qmax) ? qa2 : qmax;
        imax = (qa3 > qmax) ? 3 : imax;  qmax = (qa3 > qmax) ? qa3 : qmax;

        bool b0 = (imax == 0), b1 = (imax == 1), b2 = (imax == 2);
        float cand0 = b0 ? qa0 * qa0 : (b1 ? m21 - m12 : (b2 ? m02 - m20 : m10 - m01));
        float cand1 = b0 ? m21 - m12 : (b1 ? qa1 * qa1 : (b2 ? m10 + m01 : m20 + m02));
        float cand2 = b0 ? m02 - m20 : (b1 ? m01 + m10 : (b2 ? qa2 * qa2 : m21 + m12));
        float cand3 = b0 ? m10 - m01 : (b1 ? m02 + m20 : (b2 ? m12 + m21 : qa3 * qa3));

        float invd = __fdividef(1.0f, 2.0f * fmaxf(qmax, 0.1f));

        size_t tv = (size_t)t * V_VERTS + v;
        ((float4*)rot_out)[tv] = make_float4(cand0 * invd, cand1 * invd,
                                             cand2 * invd, cand3 * invd);
        trn_out[tv * 3 + 0] = d0x - c0x;
        trn_out[tv * 3 + 1] = d0y - c0y;
        trn_out[tv * 3 + 2] = d0z - c0z;
    }
}

extern "C" void kernel_launch(void* const* d_in, const int* in_sizes, int n_in,
                              void* d_out, int out_size) {
    const float* canon  = (const float*)d_in[0];
    const float* deform = (const float*)d_in[1];
    const int*   neigh  = (const int*)d_in[2];
    const int*   nmask  = (const int*)d_in[3];
    float* out = (float*)d_out;
    float* rot_out = out;                                   // [T*V, 4]
    float* trn_out = out + (size_t)T_FRAMES * V_VERTS * 4;  // [T*V, 3]

    static bool attr_set = false;
    if (!attr_set) {
        cudaFuncSetAttribute(se3_extract_kernel,
                             cudaFuncAttributeMaxDynamicSharedMemorySize, SMEM_BYTES);
        attr_set = true;
    }

    int pack_n = K_NBR * V_VERTS;
    pack_kernel<<<(pack_n + 255) / 256, 256>>>(neigh, nmask);
    se3_extract_kernel<<<T_FRAMES, BLOCK, SMEM_BYTES>>>(canon, deform, rot_out, trn_out);
}